// round 2
// baseline (speedup 1.0000x reference)
#include <cuda_runtime.h>
#include <cstdint>

// Problem constants
#define NPTS    32768
#define KSEL    1024
#define BATCH   8
#define CFEAT   128
#define CLUSTER 8
#define PPC     (NPTS / CLUSTER)   // 4096 points per CTA
#define THREADS 512
#define PPT     (PPC / THREADS)    // 8 points per thread
#define NWARPS  (THREADS / 32)     // 16

// Selected indices scratch (device global: no allocation allowed)
__device__ int g_idx[BATCH * KSEL];

// ---------------- PTX helpers ----------------
__device__ __forceinline__ unsigned redux_max_u32(unsigned v) {
    unsigned r;
    asm volatile("redux.sync.max.u32 %0, %1, 0xffffffff;" : "=r"(r) : "r"(v));
    return r;
}
__device__ __forceinline__ uint32_t smem_u32(const void* p) {
    uint32_t a;
    asm("{ .reg .u64 t; cvta.to.shared.u64 t, %1; cvt.u32.u64 %0, t; }"
        : "=r"(a) : "l"(p));
    return a;
}
__device__ __forceinline__ uint32_t mapa_u32(uint32_t a, uint32_t rank) {
    uint32_t d;
    asm("mapa.shared::cluster.u32 %0, %1, %2;" : "=r"(d) : "r"(a), "r"(rank));
    return d;
}
__device__ __forceinline__ unsigned ld_cl_b32(uint32_t a) {
    unsigned v;
    asm volatile("ld.shared::cluster.b32 %0, [%1];" : "=r"(v) : "r"(a));
    return v;
}
#define CLUSTER_ARR() asm volatile("barrier.cluster.arrive.aligned;" ::: "memory")
#define CLUSTER_WT()  asm volatile("barrier.cluster.wait.aligned;"   ::: "memory")

// ---------------- FPS kernel ----------------
// One cluster of 8 CTAs per batch. Points + running min-distances live in
// registers. No dynamic smem (avoids the >48KB opt-in that broke capture).
// Winner coords are pushed into the cluster payload by the thread that OWNS
// the winning point in registers (identified after the block reduce).
__global__ void __launch_bounds__(THREADS, 1) __cluster_dims__(CLUSTER, 1, 1)
fps_kernel(const float* __restrict__ xyz)
{
    __shared__ unsigned long long warpbest[NWARPS];
    __shared__ __align__(16) unsigned pay[16];   // 2 parity slots x 8 words (uses 5)
    __shared__ __align__(16) unsigned res[4];    // {idx, x, y, z}
    __shared__ unsigned bb[2];                   // block winner {enc, valbits}

    const int tid  = threadIdx.x;
    const int lane = tid & 31;
    const int wid  = tid >> 5;
    const int b    = blockIdx.x / CLUSTER;
    const int rank = blockIdx.x - b * CLUSTER;

    const float* X = xyz + (size_t)b * 3 * NPTS;
    const float* Y = X + NPTS;
    const float* Z = Y + NPTS;

    const int base = rank * PPC + tid * PPT;     // first batch-local point of this thread

    float px[PPT], py[PPT], pz[PPT], dd[PPT];
    {
        const float4* X4 = (const float4*)(X + base);
        const float4* Y4 = (const float4*)(Y + base);
        const float4* Z4 = (const float4*)(Z + base);
        float4 a0 = X4[0], a1 = X4[1];
        float4 b0 = Y4[0], b1 = Y4[1];
        float4 c0 = Z4[0], c1 = Z4[1];
        px[0]=a0.x; px[1]=a0.y; px[2]=a0.z; px[3]=a0.w; px[4]=a1.x; px[5]=a1.y; px[6]=a1.z; px[7]=a1.w;
        py[0]=b0.x; py[1]=b0.y; py[2]=b0.z; py[3]=b0.w; py[4]=b1.x; py[5]=b1.y; py[6]=b1.z; py[7]=b1.w;
        pz[0]=c0.x; pz[1]=c0.y; pz[2]=c0.z; pz[3]=c0.w; pz[4]=c1.x; pz[5]=c1.y; pz[6]=c1.z; pz[7]=c1.w;
    }
    const float INF = __int_as_float(0x7f800000);
#pragma unroll
    for (int j = 0; j < PPT; j++) dd[j] = INF;

    // First selected point is index 0 (reference starts at cur = 0).
    float cx = X[0], cy = Y[0], cz = Z[0];
    if (rank == 0 && tid == 0) g_idx[b * KSEL] = 0;

    const uint32_t pay_addr = smem_u32(pay);

    for (int k = 0; k < KSEL - 1; k++) {
        // ---- 1. min-dist update + thread-local argmax (packed key) ----
        unsigned long long best = 0ull;
#pragma unroll
        for (int j = 0; j < PPT; j++) {
            float dx = px[j] - cx;
            float dy = py[j] - cy;
            float dz = pz[j] - cz;
            // Match XLA: ((dx*dx + dy*dy) + dz*dz), no FMA contraction.
            float d = __fadd_rn(__fadd_rn(__fmul_rn(dx, dx), __fmul_rn(dy, dy)),
                                __fmul_rn(dz, dz));
            d = fminf(dd[j], d);
            dd[j] = d;
            unsigned enc = 0xFFFFFFFFu - (unsigned)(base + j);  // max enc == min idx
            unsigned long long key =
                ((unsigned long long)__float_as_uint(d) << 32) | enc;
            best = key > best ? key : best;
        }

        // ---- 2. warp reduce (max dist, tie -> min index) ----
        unsigned vb  = (unsigned)(best >> 32);
        unsigned enc = (unsigned)best;
        unsigned mvb  = redux_max_u32(vb);
        unsigned menc = redux_max_u32(vb == mvb ? enc : 0u);
        if (lane == 0) warpbest[wid] = ((unsigned long long)mvb << 32) | menc;
        __syncthreads();

        const int parity = k & 1;

        // ---- 3. block reduce (warp0) -> publish block winner key ----
        if (wid == 0) {
            unsigned wvb = 0, wenc = 0;
            if (lane < NWARPS) {
                unsigned long long w = warpbest[lane];
                wvb  = (unsigned)(w >> 32);
                wenc = (unsigned)w;
            }
            unsigned bvb  = redux_max_u32(wvb);
            unsigned benc = redux_max_u32(wvb == bvb ? wenc : 0u);
            if (lane == 0) { bb[0] = benc; bb[1] = bvb; }
        }
        __syncthreads();

        // ---- 4. owner of the winning point writes the cluster payload ----
        {
            unsigned benc = bb[0];
            int loc = (int)(~benc) - rank * PPC;   // block winner is always local
            if ((loc >> 3) == tid) {               // PPT == 8
                int j = loc & 7;
                unsigned* slot = pay + parity * 8;
                slot[0] = benc;
                slot[1] = bb[1];
                slot[2] = __float_as_uint(px[j]);
                slot[3] = __float_as_uint(py[j]);
                slot[4] = __float_as_uint(pz[j]);
            }
        }

        // ---- 5. cluster barrier, then warp0 pulls all 8 payloads via DSMEM ----
        CLUSTER_ARR();
        CLUSTER_WT();

        if (wid == 0) {
            unsigned cvb = 0, cenc = 0, ux = 0, uy = 0, uz = 0;
            if (lane < CLUSTER) {
                uint32_t ra = mapa_u32(pay_addr + parity * 32, (uint32_t)lane);
                cenc = ld_cl_b32(ra + 0);
                cvb  = ld_cl_b32(ra + 4);
                ux   = ld_cl_b32(ra + 8);
                uy   = ld_cl_b32(ra + 12);
                uz   = ld_cl_b32(ra + 16);
            }
            unsigned gvb  = redux_max_u32(cvb);
            unsigned genc = redux_max_u32(cvb == gvb ? cenc : 0u);
            // exactly one lane holds the (gvb, genc) winner (indices are unique)
            if (lane < CLUSTER && cvb == gvb && cenc == genc) {
                res[0] = ~genc;   // winning batch-local index
                res[1] = ux;
                res[2] = uy;
                res[3] = uz;
            }
        }
        __syncthreads();

        // ---- 6. broadcast result; record index ----
        cx = __uint_as_float(res[1]);
        cy = __uint_as_float(res[2]);
        cz = __uint_as_float(res[3]);
        if (rank == 0 && tid == 0) g_idx[b * KSEL + k + 1] = (int)res[0];
    }
}

// ---------------- gather kernel ----------------
// out[0 .. B*3*K)            = node_static[b][c][k]  = xyz [b][c][idx[b][k]]
// out[B*3*K .. B*3*K+B*C*K)  = node_feature[b][c][k] = feat[b][c][idx[b][k]]
__global__ void gather_kernel(const float* __restrict__ xyz,
                              const float* __restrict__ feat,
                              float* __restrict__ out)
{
    const int TOT = BATCH * (3 + CFEAT) * KSEL;  // 1073152
    int t = blockIdx.x * blockDim.x + threadIdx.x;
    if (t >= TOT) return;
    int k   = t & (KSEL - 1);
    int row = t >> 10;
    int b   = row / (3 + CFEAT);
    int c   = row - b * (3 + CFEAT);
    int idx = g_idx[b * KSEL + k];
    if (c < 3) {
        out[((size_t)b * 3 + c) * KSEL + k] =
            xyz[((size_t)b * 3 + c) * NPTS + idx];
    } else {
        int cf = c - 3;
        out[(size_t)BATCH * 3 * KSEL + ((size_t)b * CFEAT + cf) * KSEL + k] =
            feat[((size_t)b * CFEAT + cf) * NPTS + idx];
    }
}

// ---------------- launch ----------------
extern "C" void kernel_launch(void* const* d_in, const int* in_sizes, int n_in,
                              void* d_out, int out_size)
{
    const float* xyz  = (const float*)d_in[0];
    const float* feat = (const float*)d_in[1];
    // Defensive: xyz is the smaller tensor (B*3*N vs B*C*N).
    if (n_in >= 2 && in_sizes[0] > in_sizes[1]) {
        const float* tmp = xyz; xyz = feat; feat = tmp;
    }
    float* out = (float*)d_out;

    fps_kernel<<<BATCH * CLUSTER, THREADS>>>(xyz);

    const int tot = BATCH * (3 + CFEAT) * KSEL;
    gather_kernel<<<(tot + 255) / 256, 256>>>(xyz, feat, out);
}

// round 5
// speedup vs baseline: 1.0192x; 1.0192x over previous
#include <cuda_runtime.h>
#include <cstdint>

// Problem constants
#define NPTS    32768
#define KSEL    1024
#define BATCH   8
#define CFEAT   128
#define CLUSTER 8
#define PPC     (NPTS / CLUSTER)   // 4096 points per CTA
#define THREADS 512
#define PPT     (PPC / THREADS)    // 8 points per thread
#define NWARPS  (THREADS / 32)     // 16

typedef unsigned long long u64;

// Selected indices scratch (device global: no allocation allowed)
__device__ int g_idx[BATCH * KSEL];

// ---------------- PTX helpers ----------------
__device__ __forceinline__ unsigned redux_max_u32(unsigned v) {
    unsigned r;
    asm volatile("redux.sync.max.u32 %0, %1, 0xffffffff;" : "=r"(r) : "r"(v));
    return r;
}
__device__ __forceinline__ uint32_t smem_u32(const void* p) {
    uint32_t a;
    asm("{ .reg .u64 t; cvta.to.shared.u64 t, %1; cvt.u32.u64 %0, t; }"
        : "=r"(a) : "l"(p));
    return a;
}
__device__ __forceinline__ uint32_t mapa_u32(uint32_t a, uint32_t rank) {
    uint32_t d;
    asm("mapa.shared::cluster.u32 %0, %1, %2;" : "=r"(d) : "r"(a), "r"(rank));
    return d;
}
__device__ __forceinline__ unsigned ld_cl_b32(uint32_t a) {
    unsigned v;
    asm volatile("ld.shared::cluster.b32 %0, [%1];" : "=r"(v) : "r"(a));
    return v;
}
#define CLUSTER_ARR() asm volatile("barrier.cluster.arrive.aligned;" ::: "memory")
#define CLUSTER_WT()  asm volatile("barrier.cluster.wait.aligned;"   ::: "memory")

// ---------------- FPS kernel ----------------
// One cluster of 8 CTAs per batch. Structure identical to the known-passing
// R2 kernel (barrier.cluster + mapa pull exchange, parity-buffered payload
// slots, 3 __syncthreads/iter). Single functional change: winner-coordinate
// extraction uses predicated STATIC register indices + shfl, so px/py/pz/dd
// stay register-resident (R2's dynamic px[loc&7] demoted them to local mem).
__global__ void __launch_bounds__(THREADS, 1) __cluster_dims__(CLUSTER, 1, 1)
fps_kernel(const float* __restrict__ xyz)
{
    __shared__ u64 warpbest[NWARPS];
    __shared__ __align__(16) unsigned pay[16];   // 2 parity slots x 8 words (uses 5)
    __shared__ __align__(16) unsigned res[4];    // {idx, x, y, z}
    __shared__ unsigned bb[2];                   // block winner {enc, valbits}

    const int tid  = threadIdx.x;
    const int lane = tid & 31;
    const int wid  = tid >> 5;
    const int b    = blockIdx.x / CLUSTER;
    const int rank = blockIdx.x - b * CLUSTER;

    const float* X = xyz + (size_t)b * 3 * NPTS;
    const float* Y = X + NPTS;
    const float* Z = Y + NPTS;

    const int base  = rank * PPC + tid * PPT;   // first batch-local point of this thread
    const int lbase = tid * PPT;                // CTA-local index of first point

    float px[PPT], py[PPT], pz[PPT], dd[PPT];
    {
        const float4* X4 = (const float4*)(X + base);
        const float4* Y4 = (const float4*)(Y + base);
        const float4* Z4 = (const float4*)(Z + base);
        float4 a0 = X4[0], a1 = X4[1];
        float4 b0 = Y4[0], b1 = Y4[1];
        float4 c0 = Z4[0], c1 = Z4[1];
        px[0]=a0.x; px[1]=a0.y; px[2]=a0.z; px[3]=a0.w; px[4]=a1.x; px[5]=a1.y; px[6]=a1.z; px[7]=a1.w;
        py[0]=b0.x; py[1]=b0.y; py[2]=b0.z; py[3]=b0.w; py[4]=b1.x; py[5]=b1.y; py[6]=b1.z; py[7]=b1.w;
        pz[0]=c0.x; pz[1]=c0.y; pz[2]=c0.z; pz[3]=c0.w; pz[4]=c1.x; pz[5]=c1.y; pz[6]=c1.z; pz[7]=c1.w;
    }
    const float INF = __int_as_float(0x7f800000);
#pragma unroll
    for (int j = 0; j < PPT; j++) dd[j] = INF;

    // First selected point is index 0 (reference starts at cur = 0).
    float cx = X[0], cy = Y[0], cz = Z[0];
    if (rank == 0 && tid == 0) g_idx[b * KSEL] = 0;

    const uint32_t pay_addr = smem_u32(pay);

    for (int k = 0; k < KSEL - 1; k++) {
        // ---- 1. min-dist update + thread-local argmax (static indices only) ----
        float bestd = -1.0f;
        int   bestj = 0;
#pragma unroll
        for (int j = 0; j < PPT; j++) {
            float dx = px[j] - cx;
            float dy = py[j] - cy;
            float dz = pz[j] - cz;
            // Match XLA: ((dx*dx + dy*dy) + dz*dz), no FMA contraction.
            float d = __fadd_rn(__fadd_rn(__fmul_rn(dx, dx), __fmul_rn(dy, dy)),
                                __fmul_rn(dz, dz));
            d = fminf(dd[j], d);
            dd[j] = d;
            if (d > bestd) { bestd = d; bestj = j; }   // strict > keeps lowest j on ties
        }
        unsigned vb  = __float_as_uint(bestd);          // d >= 0 => uint order == float order
        unsigned enc = 0xFFFFFFFFu - (unsigned)(base + bestj);  // max enc == min idx

        // ---- 2. warp reduce (max dist, tie -> min index) ----
        unsigned mvb  = redux_max_u32(vb);
        unsigned menc = redux_max_u32(vb == mvb ? enc : 0u);
        if (lane == 0) warpbest[wid] = ((u64)mvb << 32) | menc;
        __syncthreads();

        const int parity = k & 1;

        // ---- 3. block reduce (warp0) -> publish block winner key ----
        if (wid == 0) {
            unsigned wvb = 0, wenc = 0;
            if (lane < NWARPS) {
                u64 w = warpbest[lane];
                wvb  = (unsigned)(w >> 32);
                wenc = (unsigned)w;
            }
            unsigned bvb  = redux_max_u32(wvb);
            unsigned benc = redux_max_u32(wvb == bvb ? wenc : 0u);
            if (lane == 0) { bb[0] = benc; bb[1] = bvb; }
        }
        __syncthreads();

        // ---- 4. owner warp extracts coords (predicated static idx) + lane0 writes payload ----
        {
            unsigned benc = bb[0];
            int loc = (int)(0xFFFFFFFFu - benc) - rank * PPC;  // block winner, CTA-local
            if (wid == (loc >> 8)) {                           // loc / (PPT*32) == owner warp
                int myrel = loc - lbase;                       // 0..7 iff this thread owns it
                float wx = 0.f, wy = 0.f, wz = 0.f;
#pragma unroll
                for (int j = 0; j < PPT; j++) {
                    if (myrel == j) { wx = px[j]; wy = py[j]; wz = pz[j]; }
                }
                int ownlane = (loc >> 3) & 31;
                wx = __shfl_sync(0xffffffffu, wx, ownlane);
                wy = __shfl_sync(0xffffffffu, wy, ownlane);
                wz = __shfl_sync(0xffffffffu, wz, ownlane);
                if (lane == 0) {
                    unsigned* slot = pay + parity * 8;
                    slot[0] = benc;
                    slot[1] = bb[1];
                    slot[2] = __float_as_uint(wx);
                    slot[3] = __float_as_uint(wy);
                    slot[4] = __float_as_uint(wz);
                }
            }
        }

        // ---- 5. cluster barrier, then warp0 pulls all 8 payloads via DSMEM ----
        CLUSTER_ARR();
        CLUSTER_WT();

        if (wid == 0) {
            unsigned cvb = 0, cenc = 0, ux = 0, uy = 0, uz = 0;
            if (lane < CLUSTER) {
                uint32_t ra = mapa_u32(pay_addr + parity * 32, (uint32_t)lane);
                cenc = ld_cl_b32(ra + 0);
                cvb  = ld_cl_b32(ra + 4);
                ux   = ld_cl_b32(ra + 8);
                uy   = ld_cl_b32(ra + 12);
                uz   = ld_cl_b32(ra + 16);
            }
            unsigned gvb  = redux_max_u32(cvb);
            unsigned genc = redux_max_u32(cvb == gvb ? cenc : 0u);
            // exactly one lane holds the (gvb, genc) winner (indices are unique)
            if (lane < CLUSTER && cvb == gvb && cenc == genc) {
                res[0] = 0xFFFFFFFFu - genc;   // winning batch-local index
                res[1] = ux;
                res[2] = uy;
                res[3] = uz;
            }
        }
        __syncthreads();

        // ---- 6. broadcast result; record index ----
        cx = __uint_as_float(res[1]);
        cy = __uint_as_float(res[2]);
        cz = __uint_as_float(res[3]);
        if (rank == 0 && tid == 0) g_idx[b * KSEL + k + 1] = (int)res[0];
    }
}

// ---------------- gather kernel ----------------
// out[0 .. B*3*K)            = node_static[b][c][k]  = xyz [b][c][idx[b][k]]
// out[B*3*K .. B*3*K+B*C*K)  = node_feature[b][c][k] = feat[b][c][idx[b][k]]
__global__ void gather_kernel(const float* __restrict__ xyz,
                              const float* __restrict__ feat,
                              float* __restrict__ out)
{
    const int TOT = BATCH * (3 + CFEAT) * KSEL;  // 1073152
    int t = blockIdx.x * blockDim.x + threadIdx.x;
    if (t >= TOT) return;
    int k   = t & (KSEL - 1);
    int row = t >> 10;
    int b   = row / (3 + CFEAT);
    int c   = row - b * (3 + CFEAT);
    int idx = g_idx[b * KSEL + k];
    if (c < 3) {
        out[((size_t)b * 3 + c) * KSEL + k] =
            xyz[((size_t)b * 3 + c) * NPTS + idx];
    } else {
        int cf = c - 3;
        out[(size_t)BATCH * 3 * KSEL + ((size_t)b * CFEAT + cf) * KSEL + k] =
            feat[((size_t)b * CFEAT + cf) * NPTS + idx];
    }
}

// ---------------- launch ----------------
extern "C" void kernel_launch(void* const* d_in, const int* in_sizes, int n_in,
                              void* d_out, int out_size)
{
    const float* xyz  = (const float*)d_in[0];
    const float* feat = (const float*)d_in[1];
    // Defensive: xyz is the smaller tensor (B*3*N vs B*C*N).
    if (n_in >= 2 && in_sizes[0] > in_sizes[1]) {
        const float* tmp = xyz; xyz = feat; feat = tmp;
    }
    float* out = (float*)d_out;

    fps_kernel<<<BATCH * CLUSTER, THREADS>>>(xyz);

    const int tot = BATCH * (3 + CFEAT) * KSEL;
    gather_kernel<<<(tot + 255) / 256, 256>>>(xyz, feat, out);
}

// round 9
// speedup vs baseline: 1.0541x; 1.0342x over previous
#include <cuda_runtime.h>
#include <cstdint>

// Problem constants
#define NPTS    32768
#define KSEL    1024
#define BATCH   8
#define CFEAT   128
#define CLUSTER 8
#define PPC     (NPTS / CLUSTER)   // 4096 points per CTA
#define THREADS 512
#define PPT     (PPC / THREADS)    // 8 points per thread
#define NPAIR   (PPT / 2)          // 4 packed f32x2 pairs per thread
#define NWARPS  (THREADS / 32)     // 16

typedef unsigned long long u64;

// Selected indices scratch (device global: no allocation allowed)
__device__ int g_idx[BATCH * KSEL];

// ---------------- PTX helpers ----------------
__device__ __forceinline__ unsigned redux_max_u32(unsigned v) {
    unsigned r;
    asm volatile("redux.sync.max.u32 %0, %1, 0xffffffff;" : "=r"(r) : "r"(v));
    return r;
}
__device__ __forceinline__ uint32_t smem_u32(const void* p) {
    uint32_t a;
    asm("{ .reg .u64 t; cvta.to.shared.u64 t, %1; cvt.u32.u64 %0, t; }"
        : "=r"(a) : "l"(p));
    return a;
}
__device__ __forceinline__ uint32_t mapa_u32(uint32_t a, uint32_t rank) {
    uint32_t d;
    asm("mapa.shared::cluster.u32 %0, %1, %2;" : "=r"(d) : "r"(a), "r"(rank));
    return d;
}
__device__ __forceinline__ unsigned ld_cl_b32(uint32_t a) {
    unsigned v;
    asm volatile("ld.shared::cluster.b32 %0, [%1];" : "=r"(v) : "r"(a));
    return v;
}
#define CLUSTER_ARR() asm volatile("barrier.cluster.arrive.aligned;" ::: "memory")
#define CLUSTER_WT()  asm volatile("barrier.cluster.wait.aligned;"   ::: "memory")

// Packed f32x2 ops (PTX ISA: only add/mul/fma have f32x2 forms on sm_100a).
// Register-only arithmetic — cannot fault. Verified to compile+launch in R7.
__device__ __forceinline__ u64 f2_add(u64 a, u64 b) {
    u64 r; asm("add.rn.f32x2 %0, %1, %2;" : "=l"(r) : "l"(a), "l"(b)); return r;
}
__device__ __forceinline__ u64 f2_mul(u64 a, u64 b) {
    u64 r; asm("mul.rn.f32x2 %0, %1, %2;" : "=l"(r) : "l"(a), "l"(b)); return r;
}
__device__ __forceinline__ u64 pack2(float lo, float hi) {
    u64 r; asm("mov.b64 %0, {%1, %2};" : "=l"(r) : "f"(lo), "f"(hi)); return r;
}
__device__ __forceinline__ void unpack2(u64 v, float& lo, float& hi) {
    asm("mov.b64 {%0, %1}, %2;" : "=f"(lo), "=f"(hi) : "l"(v));
}

// ---------------- FPS kernel ----------------
// EXACT R5 structure (proven passing: warp0-only DSMEM pull, bb/res smem
// broadcasts, 3 __syncthreads + 1 cluster barrier per iteration).
// Single delta vs R5: the update loop uses packed f32x2 add/mul for the
// diff/square/sum chain (bitwise-identical per-lane IEEE rn arithmetic).
__global__ void __launch_bounds__(THREADS, 1) __cluster_dims__(CLUSTER, 1, 1)
fps_kernel(const float* __restrict__ xyz)
{
    __shared__ u64 warpbest[NWARPS];
    __shared__ __align__(16) unsigned pay[16];   // 2 parity slots x 8 words (uses 5)
    __shared__ __align__(16) unsigned res[4];    // {idx, x, y, z}
    __shared__ unsigned bb[2];                   // block winner {enc, valbits}

    const int tid  = threadIdx.x;
    const int lane = tid & 31;
    const int wid  = tid >> 5;
    const int b    = blockIdx.x / CLUSTER;
    const int rank = blockIdx.x - b * CLUSTER;

    const float* X = xyz + (size_t)b * 3 * NPTS;
    const float* Y = X + NPTS;
    const float* Z = Y + NPTS;

    const int base  = rank * PPC + tid * PPT;   // first batch-local point of this thread
    const int lbase = tid * PPT;                // CTA-local index of first point

    // Load 8 points, keep packed as 4 f32x2 pairs per coordinate.
    u64 px2[NPAIR], py2[NPAIR], pz2[NPAIR];
    float dd[PPT];
    {
        const float4* X4 = (const float4*)(X + base);
        const float4* Y4 = (const float4*)(Y + base);
        const float4* Z4 = (const float4*)(Z + base);
        float4 a0 = X4[0], a1 = X4[1];
        float4 b0 = Y4[0], b1 = Y4[1];
        float4 c0 = Z4[0], c1 = Z4[1];
        px2[0] = pack2(a0.x, a0.y); px2[1] = pack2(a0.z, a0.w);
        px2[2] = pack2(a1.x, a1.y); px2[3] = pack2(a1.z, a1.w);
        py2[0] = pack2(b0.x, b0.y); py2[1] = pack2(b0.z, b0.w);
        py2[2] = pack2(b1.x, b1.y); py2[3] = pack2(b1.z, b1.w);
        pz2[0] = pack2(c0.x, c0.y); pz2[1] = pack2(c0.z, c0.w);
        pz2[2] = pack2(c1.x, c1.y); pz2[3] = pack2(c1.z, c1.w);
    }
    const float INF = __int_as_float(0x7f800000);
#pragma unroll
    for (int j = 0; j < PPT; j++) dd[j] = INF;

    // First selected point is index 0 (reference starts at cur = 0).
    float cx = X[0], cy = Y[0], cz = Z[0];
    if (rank == 0 && tid == 0) g_idx[b * KSEL] = 0;

    const uint32_t pay_addr = smem_u32(pay);

    for (int k = 0; k < KSEL - 1; k++) {
        // ---- 1. packed diff/square/sum + scalar min/argmax ----
        // Exact scalar semantics: dx = px + (-cx) == px - cx (IEEE exact),
        // d = ((dx*dx + dy*dy) + dz*dz) all rn per lane, dd = fminf(dd, d).
        const u64 ncx = pack2(-cx, -cx);
        const u64 ncy = pack2(-cy, -cy);
        const u64 ncz = pack2(-cz, -cz);
        float bestd = -1.0f;
        int   bestj = 0;
#pragma unroll
        for (int p = 0; p < NPAIR; p++) {
            u64 dx = f2_add(px2[p], ncx);
            u64 dy = f2_add(py2[p], ncy);
            u64 dz = f2_add(pz2[p], ncz);
            u64 s  = f2_add(f2_add(f2_mul(dx, dx), f2_mul(dy, dy)), f2_mul(dz, dz));
            float s0, s1;
            unpack2(s, s0, s1);                    // register aliasing, ~free
            float d0 = fminf(dd[2 * p],     s0);
            float d1 = fminf(dd[2 * p + 1], s1);
            dd[2 * p]     = d0;
            dd[2 * p + 1] = d1;
            if (d0 > bestd) { bestd = d0; bestj = 2 * p; }      // strict > keeps lowest j
            if (d1 > bestd) { bestd = d1; bestj = 2 * p + 1; }
        }
        unsigned vb  = __float_as_uint(bestd);                   // bestd >= 0
        unsigned enc = 0xFFFFFFFFu - (unsigned)(base + bestj);   // max enc == min idx

        // ---- 2. warp reduce (max dist, tie -> min index) ----
        unsigned mvb  = redux_max_u32(vb);
        unsigned menc = redux_max_u32(vb == mvb ? enc : 0u);
        if (lane == 0) warpbest[wid] = ((u64)mvb << 32) | menc;
        __syncthreads();

        const int parity = k & 1;

        // ---- 3. block reduce (warp0) -> publish block winner key ----
        if (wid == 0) {
            unsigned wvb = 0, wenc = 0;
            if (lane < NWARPS) {
                u64 w = warpbest[lane];
                wvb  = (unsigned)(w >> 32);
                wenc = (unsigned)w;
            }
            unsigned bvb  = redux_max_u32(wvb);
            unsigned benc = redux_max_u32(wvb == bvb ? wenc : 0u);
            if (lane == 0) { bb[0] = benc; bb[1] = bvb; }
        }
        __syncthreads();

        // ---- 4. owner warp extracts coords (predicated static idx) + lane0 writes payload ----
        {
            unsigned benc = bb[0];
            int loc = (int)(0xFFFFFFFFu - benc) - rank * PPC;  // block winner, CTA-local
            if (wid == (loc >> 8)) {                           // loc / (PPT*32) == owner warp
                int myrel = loc - lbase;                       // 0..7 iff this thread owns it
                float wx = 0.f, wy = 0.f, wz = 0.f;
#pragma unroll
                for (int p = 0; p < NPAIR; p++) {
                    float lo, hi;
                    unpack2(px2[p], lo, hi);
                    if (myrel == 2 * p)     wx = lo;
                    if (myrel == 2 * p + 1) wx = hi;
                    unpack2(py2[p], lo, hi);
                    if (myrel == 2 * p)     wy = lo;
                    if (myrel == 2 * p + 1) wy = hi;
                    unpack2(pz2[p], lo, hi);
                    if (myrel == 2 * p)     wz = lo;
                    if (myrel == 2 * p + 1) wz = hi;
                }
                int ownlane = (loc >> 3) & 31;
                wx = __shfl_sync(0xffffffffu, wx, ownlane);
                wy = __shfl_sync(0xffffffffu, wy, ownlane);
                wz = __shfl_sync(0xffffffffu, wz, ownlane);
                if (lane == 0) {
                    unsigned* slot = pay + parity * 8;
                    slot[0] = benc;
                    slot[1] = bb[1];
                    slot[2] = __float_as_uint(wx);
                    slot[3] = __float_as_uint(wy);
                    slot[4] = __float_as_uint(wz);
                }
            }
        }

        // ---- 5. cluster barrier, then warp0 pulls all 8 payloads via DSMEM ----
        CLUSTER_ARR();
        CLUSTER_WT();

        if (wid == 0) {
            unsigned cvb = 0, cenc = 0, ux = 0, uy = 0, uz = 0;
            if (lane < CLUSTER) {
                uint32_t ra = mapa_u32(pay_addr + parity * 32, (uint32_t)lane);
                cenc = ld_cl_b32(ra + 0);
                cvb  = ld_cl_b32(ra + 4);
                ux   = ld_cl_b32(ra + 8);
                uy   = ld_cl_b32(ra + 12);
                uz   = ld_cl_b32(ra + 16);
            }
            unsigned gvb  = redux_max_u32(cvb);
            unsigned genc = redux_max_u32(cvb == gvb ? cenc : 0u);
            // exactly one lane holds the (gvb, genc) winner (indices are unique)
            if (lane < CLUSTER && cvb == gvb && cenc == genc) {
                res[0] = 0xFFFFFFFFu - genc;   // winning batch-local index
                res[1] = ux;
                res[2] = uy;
                res[3] = uz;
            }
        }
        __syncthreads();

        // ---- 6. broadcast result; record index ----
        cx = __uint_as_float(res[1]);
        cy = __uint_as_float(res[2]);
        cz = __uint_as_float(res[3]);
        if (rank == 0 && tid == 0) g_idx[b * KSEL + k + 1] = (int)res[0];
    }
}

// ---------------- gather kernel ----------------
__global__ void gather_kernel(const float* __restrict__ xyz,
                              const float* __restrict__ feat,
                              float* __restrict__ out)
{
    const int TOT = BATCH * (3 + CFEAT) * KSEL;  // 1073152
    int t = blockIdx.x * blockDim.x + threadIdx.x;
    if (t >= TOT) return;
    int k   = t & (KSEL - 1);
    int row = t >> 10;
    int b   = row / (3 + CFEAT);
    int c   = row - b * (3 + CFEAT);
    int idx = g_idx[b * KSEL + k];
    if (c < 3) {
        out[((size_t)b * 3 + c) * KSEL + k] =
            xyz[((size_t)b * 3 + c) * NPTS + idx];
    } else {
        int cf = c - 3;
        out[(size_t)BATCH * 3 * KSEL + ((size_t)b * CFEAT + cf) * KSEL + k] =
            feat[((size_t)b * CFEAT + cf) * NPTS + idx];
    }
}

// Tiny no-op kernel: 5 of these shift ncu's `-s 5 -c 1` window onto fps_kernel.
__global__ void dummy_kernel() {}

// ---------------- launch ----------------
extern "C" void kernel_launch(void* const* d_in, const int* in_sizes, int n_in,
                              void* d_out, int out_size)
{
    const float* xyz  = (const float*)d_in[0];
    const float* feat = (const float*)d_in[1];
    // Defensive: xyz is the smaller tensor (B*3*N vs B*C*N).
    if (n_in >= 2 && in_sizes[0] > in_sizes[1]) {
        const float* tmp = xyz; xyz = feat; feat = tmp;
    }
    float* out = (float*)d_out;

    // ncu alignment: launches 0-4 are no-ops so launch #5 (profiled) is fps.
    for (int i = 0; i < 5; i++) dummy_kernel<<<1, 32>>>();

    fps_kernel<<<BATCH * CLUSTER, THREADS>>>(xyz);

    const int tot = BATCH * (3 + CFEAT) * KSEL;
    gather_kernel<<<(tot + 255) / 256, 256>>>(xyz, feat, out);
}

// round 12
// speedup vs baseline: 1.0935x; 1.0374x over previous
#include <cuda_runtime.h>
#include <cstdint>

// Problem constants
#define NPTS    32768
#define KSEL    1024
#define BATCH   8
#define CFEAT   128
#define CLUSTER 8
#define PPC     (NPTS / CLUSTER)   // 4096 points per CTA
#define THREADS 512
#define PPT     (PPC / THREADS)    // 8 points per thread
#define NPAIR   (PPT / 2)          // 4 packed f32x2 pairs per thread
#define NWARPS  (THREADS / 32)     // 16

typedef unsigned long long u64;

// Selected indices scratch (device global: no allocation allowed)
__device__ int g_idx[BATCH * KSEL];

// ---------------- PTX helpers ----------------
// HARD RULE from the R0-R11 failure taxonomy: remote (shared::cluster)
// accesses are 32-bit ONLY. Every kernel that used 64-bit DSMEM ops
// (ld/st.shared::cluster.b64, st.async.b64) died; every b32-only kernel passed.
__device__ __forceinline__ unsigned redux_max_u32(unsigned v) {
    unsigned r;
    asm volatile("redux.sync.max.u32 %0, %1, 0xffffffff;" : "=r"(r) : "r"(v));
    return r;
}
__device__ __forceinline__ uint32_t smem_u32(const void* p) {
    uint32_t a;
    asm("{ .reg .u64 t; cvta.to.shared.u64 t, %1; cvt.u32.u64 %0, t; }"
        : "=r"(a) : "l"(p));
    return a;
}
__device__ __forceinline__ uint32_t mapa_u32(uint32_t a, uint32_t rank) {
    uint32_t d;
    asm("mapa.shared::cluster.u32 %0, %1, %2;" : "=r"(d) : "r"(a), "r"(rank));
    return d;
}
__device__ __forceinline__ unsigned ld_cl_b32(uint32_t a) {
    unsigned v;
    asm volatile("ld.shared::cluster.b32 %0, [%1];" : "=r"(v) : "r"(a));
    return v;
}
#define CLUSTER_ARR() asm volatile("barrier.cluster.arrive.aligned;" ::: "memory")
#define CLUSTER_WT()  asm volatile("barrier.cluster.wait.aligned;"   ::: "memory")

// Packed f32x2 ops (PTX ISA: only add/mul/fma have f32x2 forms on sm_100a).
__device__ __forceinline__ u64 f2_add(u64 a, u64 b) {
    u64 r; asm("add.rn.f32x2 %0, %1, %2;" : "=l"(r) : "l"(a), "l"(b)); return r;
}
__device__ __forceinline__ u64 f2_mul(u64 a, u64 b) {
    u64 r; asm("mul.rn.f32x2 %0, %1, %2;" : "=l"(r) : "l"(a), "l"(b)); return r;
}
__device__ __forceinline__ u64 pack2(float lo, float hi) {
    u64 r; asm("mov.b64 %0, {%1, %2};" : "=l"(r) : "f"(lo), "f"(hi)); return r;
}
__device__ __forceinline__ void unpack2(u64 v, float& lo, float& hi) {
    asm("mov.b64 {%0, %1}, %2;" : "=f"(lo), "=f"(hi) : "l"(v));
}

// ---------------- FPS kernel ----------------
// R9 structure (proven: warp0-only b32 DSMEM pull after per-iter cluster
// barrier, res smem broadcast + trailing __syncthreads). Delta vs R9: the
// block reduce is computed redundantly by EVERY warp from warpbest[]
// (redux.sync is deterministic -> identical result in all warps), removing
// the bb[] publish round-trip and one __syncthreads. Two __syncthreads +
// one cluster barrier per iteration.
__global__ void __launch_bounds__(THREADS, 1) __cluster_dims__(CLUSTER, 1, 1)
fps_kernel(const float* __restrict__ xyz)
{
    __shared__ u64 warpbest[NWARPS];
    __shared__ __align__(16) unsigned pay[16];   // 2 parity slots x 8 words (uses 5)
    __shared__ __align__(16) unsigned res[4];    // {idx, x, y, z}

    const int tid  = threadIdx.x;
    const int lane = tid & 31;
    const int wid  = tid >> 5;
    const int b    = blockIdx.x / CLUSTER;
    const int rank = blockIdx.x - b * CLUSTER;

    const float* X = xyz + (size_t)b * 3 * NPTS;
    const float* Y = X + NPTS;
    const float* Z = Y + NPTS;

    const int base  = rank * PPC + tid * PPT;   // first batch-local point of this thread
    const int lbase = tid * PPT;                // CTA-local index of first point

    // Load 8 points, keep packed as 4 f32x2 pairs per coordinate.
    u64 px2[NPAIR], py2[NPAIR], pz2[NPAIR];
    float dd[PPT];
    {
        const float4* X4 = (const float4*)(X + base);
        const float4* Y4 = (const float4*)(Y + base);
        const float4* Z4 = (const float4*)(Z + base);
        float4 a0 = X4[0], a1 = X4[1];
        float4 b0 = Y4[0], b1 = Y4[1];
        float4 c0 = Z4[0], c1 = Z4[1];
        px2[0] = pack2(a0.x, a0.y); px2[1] = pack2(a0.z, a0.w);
        px2[2] = pack2(a1.x, a1.y); px2[3] = pack2(a1.z, a1.w);
        py2[0] = pack2(b0.x, b0.y); py2[1] = pack2(b0.z, b0.w);
        py2[2] = pack2(b1.x, b1.y); py2[3] = pack2(b1.z, b1.w);
        pz2[0] = pack2(c0.x, c0.y); pz2[1] = pack2(c0.z, c0.w);
        pz2[2] = pack2(c1.x, c1.y); pz2[3] = pack2(c1.z, c1.w);
    }
    const float INF = __int_as_float(0x7f800000);
#pragma unroll
    for (int j = 0; j < PPT; j++) dd[j] = INF;

    // First selected point is index 0 (reference starts at cur = 0).
    float cx = X[0], cy = Y[0], cz = Z[0];
    if (rank == 0 && tid == 0) g_idx[b * KSEL] = 0;

    const uint32_t pay_addr = smem_u32(pay);

    for (int k = 0; k < KSEL - 1; k++) {
        const int parity = k & 1;

        // ---- 1. packed diff/square/sum + scalar min/argmax ----
        // Exact scalar semantics: dx = px + (-cx) == px - cx (IEEE exact),
        // d = ((dx*dx + dy*dy) + dz*dz) all rn per lane, dd = fminf(dd, d).
        const u64 ncx = pack2(-cx, -cx);
        const u64 ncy = pack2(-cy, -cy);
        const u64 ncz = pack2(-cz, -cz);
        float bestd = -1.0f;
        int   bestj = 0;
#pragma unroll
        for (int p = 0; p < NPAIR; p++) {
            u64 dx = f2_add(px2[p], ncx);
            u64 dy = f2_add(py2[p], ncy);
            u64 dz = f2_add(pz2[p], ncz);
            u64 s  = f2_add(f2_add(f2_mul(dx, dx), f2_mul(dy, dy)), f2_mul(dz, dz));
            float s0, s1;
            unpack2(s, s0, s1);                    // register aliasing, ~free
            float d0 = fminf(dd[2 * p],     s0);
            float d1 = fminf(dd[2 * p + 1], s1);
            dd[2 * p]     = d0;
            dd[2 * p + 1] = d1;
            if (d0 > bestd) { bestd = d0; bestj = 2 * p; }      // strict > keeps lowest j
            if (d1 > bestd) { bestd = d1; bestj = 2 * p + 1; }
        }
        unsigned vb  = __float_as_uint(bestd);                   // bestd >= 0
        unsigned enc = 0xFFFFFFFFu - (unsigned)(base + bestj);   // max enc == min idx

        // ---- 2. warp reduce (max dist, tie -> min index) ----
        unsigned mvb  = redux_max_u32(vb);
        unsigned menc = redux_max_u32(vb == mvb ? enc : 0u);
        if (lane == 0) warpbest[wid] = ((u64)mvb << 32) | menc;
        __syncthreads();

        // ---- 3. block reduce (every warp, redundantly -> identical benc/bvb) ----
        unsigned wvb = 0, wenc = 0;
        if (lane < NWARPS) {
            u64 w = warpbest[lane];
            wvb  = (unsigned)(w >> 32);
            wenc = (unsigned)w;
        }
        unsigned bvb  = redux_max_u32(wvb);
        unsigned benc = redux_max_u32(wvb == bvb ? wenc : 0u);

        // ---- 4. owner warp extracts coords (predicated static idx) + lane0 writes payload ----
        {
            int loc = (int)(0xFFFFFFFFu - benc) - rank * PPC;  // block winner, CTA-local
            if (wid == (loc >> 8)) {                           // loc / (PPT*32) == owner warp
                int myrel = loc - lbase;                       // 0..7 iff this thread owns it
                float wx = 0.f, wy = 0.f, wz = 0.f;
#pragma unroll
                for (int p = 0; p < NPAIR; p++) {
                    float lo, hi;
                    unpack2(px2[p], lo, hi);
                    if (myrel == 2 * p)     wx = lo;
                    if (myrel == 2 * p + 1) wx = hi;
                    unpack2(py2[p], lo, hi);
                    if (myrel == 2 * p)     wy = lo;
                    if (myrel == 2 * p + 1) wy = hi;
                    unpack2(pz2[p], lo, hi);
                    if (myrel == 2 * p)     wz = lo;
                    if (myrel == 2 * p + 1) wz = hi;
                }
                int ownlane = (loc >> 3) & 31;
                wx = __shfl_sync(0xffffffffu, wx, ownlane);
                wy = __shfl_sync(0xffffffffu, wy, ownlane);
                wz = __shfl_sync(0xffffffffu, wz, ownlane);
                if (lane == 0) {
                    unsigned* slot = pay + parity * 8;
                    slot[0] = benc;
                    slot[1] = bvb;
                    slot[2] = __float_as_uint(wx);
                    slot[3] = __float_as_uint(wy);
                    slot[4] = __float_as_uint(wz);
                }
            }
        }

        // ---- 5. cluster barrier, then warp0 pulls all 8 payloads via DSMEM (b32) ----
        CLUSTER_ARR();
        CLUSTER_WT();

        if (wid == 0) {
            unsigned cvb = 0, cenc = 0, ux = 0, uy = 0, uz = 0;
            if (lane < CLUSTER) {
                uint32_t ra = mapa_u32(pay_addr + parity * 32, (uint32_t)lane);
                cenc = ld_cl_b32(ra + 0);
                cvb  = ld_cl_b32(ra + 4);
                ux   = ld_cl_b32(ra + 8);
                uy   = ld_cl_b32(ra + 12);
                uz   = ld_cl_b32(ra + 16);
            }
            unsigned gvb  = redux_max_u32(cvb);
            unsigned genc = redux_max_u32(cvb == gvb ? cenc : 0u);
            // exactly one lane holds the (gvb, genc) winner (indices are unique)
            if (lane < CLUSTER && cvb == gvb && cenc == genc) {
                res[0] = 0xFFFFFFFFu - genc;   // winning batch-local index
                res[1] = ux;
                res[2] = uy;
                res[3] = uz;
            }
        }
        __syncthreads();

        // ---- 6. broadcast result; record index ----
        cx = __uint_as_float(res[1]);
        cy = __uint_as_float(res[2]);
        cz = __uint_as_float(res[3]);
        if (rank == 0 && tid == 0) g_idx[b * KSEL + k + 1] = (int)res[0];
    }
}

// ---------------- gather kernel ----------------
__global__ void gather_kernel(const float* __restrict__ xyz,
                              const float* __restrict__ feat,
                              float* __restrict__ out)
{
    const int TOT = BATCH * (3 + CFEAT) * KSEL;  // 1073152
    int t = blockIdx.x * blockDim.x + threadIdx.x;
    if (t >= TOT) return;
    int k   = t & (KSEL - 1);
    int row = t >> 10;
    int b   = row / (3 + CFEAT);
    int c   = row - b * (3 + CFEAT);
    int idx = g_idx[b * KSEL + k];
    if (c < 3) {
        out[((size_t)b * 3 + c) * KSEL + k] =
            xyz[((size_t)b * 3 + c) * NPTS + idx];
    } else {
        int cf = c - 3;
        out[(size_t)BATCH * 3 * KSEL + ((size_t)b * CFEAT + cf) * KSEL + k] =
            feat[((size_t)b * CFEAT + cf) * NPTS + idx];
    }
}

// No-op kernel for ncu alignment: with 4 dummies, fps_kernel sits at profiled
// launch index 5 (R9 evidence: 5 dummies put a dummy at index 5).
__global__ void dummy_kernel() {}

// ---------------- launch ----------------
extern "C" void kernel_launch(void* const* d_in, const int* in_sizes, int n_in,
                              void* d_out, int out_size)
{
    const float* xyz  = (const float*)d_in[0];
    const float* feat = (const float*)d_in[1];
    // Defensive: xyz is the smaller tensor (B*3*N vs B*C*N).
    if (n_in >= 2 && in_sizes[0] > in_sizes[1]) {
        const float* tmp = xyz; xyz = feat; feat = tmp;
    }
    float* out = (float*)d_out;

    for (int i = 0; i < 4; i++) dummy_kernel<<<1, 32>>>();

    fps_kernel<<<BATCH * CLUSTER, THREADS>>>(xyz);

    const int tot = BATCH * (3 + CFEAT) * KSEL;
    gather_kernel<<<(tot + 255) / 256, 256>>>(xyz, feat, out);
}